// round 8
// baseline (speedup 1.0000x reference)
#include <cuda_runtime.h>
#include <cuda_bf16.h>

// S4 Vandermonde kernel: out[h,l] = 2*Re( sum_n Ceff[h,n] * w[h,n]^l )
//   w = exp(dtA), Ceff = Bc*Cc*(w-1)/A ;  H=512, NH=32, L=8192.
//
// R7: Goertzel two-term real recurrence (r_{i+1} = p r_i + q r_{i-1}) as R6,
// but perfectly balanced: grid=148 (one block/SM), 592 warps = exactly one
// warp per SMSP, each warp owns a ~221-step contiguous slice of the flattened
// (h, i) step space. Arbitrary (h, i0) start via direct per-mode exp/sincos
// (MUFU pipe) instead of power tables -> cheap setup, <=2 segments per warp.

#define HH 512
#define NHALF 32
#define LL 8192
#define WPB 4
#define NBLK 148
#define NWARPS (NBLK * WPB)          // 592
#define TOT_STEPS (HH * (LL / 32))   // 131072

typedef unsigned long long u64;

__device__ __forceinline__ u64 pk2(float lo, float hi) {
    u64 r; asm("mov.b64 %0,{%1,%2};" : "=l"(r) : "f"(lo), "f"(hi)); return r;
}
__device__ __forceinline__ void upk2(u64 v, float& lo, float& hi) {
    asm("mov.b64 {%0,%1},%2;" : "=f"(lo), "=f"(hi) : "l"(v));
}
__device__ __forceinline__ u64 f2mul(u64 a, u64 b) {
    u64 r; asm("mul.rn.f32x2 %0,%1,%2;" : "=l"(r) : "l"(a), "l"(b)); return r;
}
__device__ __forceinline__ u64 f2fma(u64 a, u64 b, u64 c) {
    u64 r; asm("fma.rn.f32x2 %0,%1,%2,%3;" : "=l"(r) : "l"(a), "l"(b), "l"(c)); return r;
}
__device__ __forceinline__ u64 f2add(u64 a, u64 b) {
    u64 r; asm("add.rn.f32x2 %0,%1,%2;" : "=l"(r) : "l"(a), "l"(b)); return r;
}

__device__ __forceinline__ float2 cmulf(float2 a, float2 b) {
    return make_float2(fmaf(a.x, b.x, -a.y * b.y), fmaf(a.x, b.y, a.y * b.x));
}

// reduction tree over 16 packed pairs -> scalar (lo+hi)
__device__ __forceinline__ float sumtree16(const u64* R) {
    u64 s0 = f2add(R[0], R[8]);
    u64 s1 = f2add(R[1], R[9]);
    u64 s2 = f2add(R[2], R[10]);
    u64 s3 = f2add(R[3], R[11]);
    u64 s4 = f2add(R[4], R[12]);
    u64 s5 = f2add(R[5], R[13]);
    u64 s6 = f2add(R[6], R[14]);
    u64 s7 = f2add(R[7], R[15]);
    s0 = f2add(s0, s4); s1 = f2add(s1, s5);
    s2 = f2add(s2, s6); s3 = f2add(s3, s7);
    s0 = f2add(s0, s2); s1 = f2add(s1, s3);
    s0 = f2add(s0, s1);
    float lo, hi; upk2(s0, lo, hi);
    return lo + hi;
}

#define PI2_HI 6.2831854820251465f
#define PI2_LO (-1.7484561e-7f)
#define INV2PI 0.15915494309189535f

// accurate sin/cos of (dim*scale) with two-float 2*pi reduction
__device__ __forceinline__ void redsc(float th, float* s, float* c) {
    float kk = rintf(th * INV2PI);
    float r  = fmaf(-kk, PI2_HI, th);
    r        = fmaf(-kk, PI2_LO, r);
    __sincosf(r, s, c);
}

// per-mode start values from the smem param rows at offset l0f
__device__ __forceinline__ void start_mode(const float4* mpn, float l0f,
                                           float& r0, float& rm,
                                           float& p,  float& q) {
    float4 a = mpn[0];   // p, q, wm32r, wm32i
    float4 b = mpn[1];   // c2r, c2i, dre, dim
    p = a.x; q = a.y;
    float sn, cs;
    redsc(b.w * l0f, &sn, &cs);          // theta = dim*l0 (same rounding as ref)
    float mg  = __expf(b.z * l0f);       // dre*l0 <= 0 -> mg <= 1, no overflow
    float zr  = mg * cs, zi = mg * sn;
    float z0r = fmaf(b.x, zr, -b.y * zi);
    float z0i = fmaf(b.x, zi,  b.y * zr);
    r0 = z0r;
    rm = fmaf(z0r, a.z, -z0i * a.w);     // zm = z0 * w^-32 (real part)
}

__global__ void __launch_bounds__(128, 1)
s4_vandermonde_kernel(const float* __restrict__ log_dt,
                      const float* __restrict__ log_A_real,
                      const float* __restrict__ A_imag,
                      const float* __restrict__ Bmat,
                      const float* __restrict__ Cmat,
                      float* __restrict__ out)
{
    // per warp, per mode: row0 = {p, q, wm32r, wm32i}, row1 = {c2r, c2i, dre, dim}
    __shared__ float4 mp[WPB][NHALF][2];

    const int w = threadIdx.x >> 5;
    const int j = threadIdx.x & 31;
    const int k = blockIdx.x * WPB + w;

    int s  = (int)(((long long)k       * TOT_STEPS) / NWARPS);
    int s1 = (int)(((long long)(k + 1) * TOT_STEPS) / NWARPS);

    while (s < s1) {
        const int h   = s >> 8;
        const int i0  = s & 255;
        const int cnt = min(s1 - s, 256 - i0);

        // ---------- phase A: lane j computes mode j params ----------
        __syncwarp();
        {
            const int n = j;
            const float dt  = __expf(log_dt[h]);
            const float ar  = -__expf(log_A_real[h * NHALF + n]);
            const float aiv = -A_imag[h * NHALF + n];
            const float dre = dt * ar;
            const float dim = dt * aiv;

            // w^1 (for Ceff)
            float s1v, c1v; redsc(dim, &s1v, &c1v);
            float mg1 = __expf(dre);
            // w^32 (for p, q and, with conjugated sign, w^-32)
            float s32, c32; redsc(32.f * dim, &s32, &c32);
            float mg32 = __expf(32.f * dre);
            float w32r = mg32 * c32, w32i = mg32 * s32;
            float p = w32r + w32r;
            float q = -fmaf(w32r, w32r, w32i * w32i);
            // w^-32, magnitude clamped: when clamp engages q has underflowed to 0
            float mgm = __expf(fminf(-32.f * dre, 60.f));
            float wmr = mgm * c32, wmi = -mgm * s32;
            // 2*Ceff = 2*Bc*Cc*(w-1)/A
            float2 w1  = make_float2(mg1 * c1v, mg1 * s1v);
            float2 num = make_float2(w1.x - 1.0f, w1.y);
            float  inv = 2.0f / fmaf(ar, ar, aiv * aiv);
            float2 ia  = make_float2(ar * inv, -aiv * inv);
            const float2* Bv = (const float2*)Bmat;
            const float2* Cv = (const float2*)Cmat;
            float2 bc  = cmulf(Bv[h * NHALF + n], Cv[h * NHALF + n]);
            float2 c2  = cmulf(cmulf(bc, num), ia);

            mp[w][n][0] = make_float4(p, q, wmr, wmi);
            mp[w][n][1] = make_float4(c2.x, c2.y, dre, dim);
        }
        __syncwarp();

        // ---------- phase B: start state at l0 = 32*i0 + j ----------
        const float l0f = (float)(i0 * 32 + j);
        u64 RB[NHALF / 2], RA[NHALF / 2], P[NHALF / 2], Q[NHALF / 2];
        #pragma unroll
        for (int m = 0; m < NHALF / 2; m++) {
            float r0a, rma, pa, qa, r0b, rmb, pb, qb;
            start_mode(&mp[w][2 * m][0],     l0f, r0a, rma, pa, qa);
            start_mode(&mp[w][2 * m + 1][0], l0f, r0b, rmb, pb, qb);
            RB[m] = pk2(r0a, r0b);
            RA[m] = pk2(rma, rmb);
            P[m]  = pk2(pa, pb);
            Q[m]  = pk2(qa, qb);
        }

        // ---------- main recurrence, 2-unrolled with role swap ----------
        float* opp = out + h * LL + i0 * 32 + j;
        int t = 0;
        for (; t + 1 < cnt; t += 2) {
            opp[0] = sumtree16(RB);                   // r_t
            #pragma unroll
            for (int m = 0; m < NHALF / 2; m++)       // RA <- r_{t+1}
                RA[m] = f2fma(P[m], RB[m], f2mul(Q[m], RA[m]));
            opp[32] = sumtree16(RA);                  // r_{t+1}
            #pragma unroll
            for (int m = 0; m < NHALF / 2; m++)       // RB <- r_{t+2}
                RB[m] = f2fma(P[m], RA[m], f2mul(Q[m], RB[m]));
            opp += 64;
        }
        if (t < cnt)
            opp[0] = sumtree16(RB);                   // odd tail

        s += cnt;
    }
}

extern "C" void kernel_launch(void* const* d_in, const int* in_sizes, int n_in,
                              void* d_out, int out_size)
{
    const float* log_dt     = (const float*)d_in[0];
    const float* log_A_real = (const float*)d_in[1];
    const float* A_imag     = (const float*)d_in[2];
    const float* Bmat       = (const float*)d_in[3];
    const float* Cmat       = (const float*)d_in[4];
    float* out = (float*)d_out;

    dim3 grid(NBLK);          // 148 blocks -> exactly one per SM
    dim3 block(32 * WPB);     // 128 threads -> one warp per SMSP
    s4_vandermonde_kernel<<<grid, block>>>(log_dt, log_A_real, A_imag,
                                           Bmat, Cmat, out);
}

// round 9
// speedup vs baseline: 1.0696x; 1.0696x over previous
#include <cuda_runtime.h>
#include <cuda_bf16.h>

// S4 Vandermonde kernel: out[h,l] = 2*Re( sum_n Ceff[h,n] * w[h,n]^l )
//   w = exp(dtA), Ceff = Bc*Cc*(w-1)/A ;  H=512, NH=32, L=8192.
//
// R8: Goertzel two-term real recurrence r_{i+1} = p r_i + q r_{i-1} with
// p = 2 Re(w^32), q = -|w^32|^2.  592 warps (148 blocks x 4) = one per SMSP;
// work partitioned at 32-step *segment* granularity (4096 segments, 6-7 per
// warp, imbalance 1.2%).  The 32-step inner loop has a STATIC trip count
// (unroll 4) so ptxas keeps f32x2 state in aligned register pairs -- R7's
// dynamic-count loop regressed into MOV/IADD soup (alu 45%).  Recurrence
// continues across segments within an h-span; params recomputed per h-span.

#define HH 512
#define NHALF 32
#define LL 8192
#define WPB 4
#define NBLK 148
#define NWARPS (NBLK * WPB)          // 592
#define SEGS_TOT 4096                // 512 h * 8 segments of 32 steps
#define SEG_STEPS 32

typedef unsigned long long u64;

__device__ __forceinline__ u64 pk2(float lo, float hi) {
    u64 r; asm("mov.b64 %0,{%1,%2};" : "=l"(r) : "f"(lo), "f"(hi)); return r;
}
__device__ __forceinline__ void upk2(u64 v, float& lo, float& hi) {
    asm("mov.b64 {%0,%1},%2;" : "=f"(lo), "=f"(hi) : "l"(v));
}
__device__ __forceinline__ u64 f2mul(u64 a, u64 b) {
    u64 r; asm("mul.rn.f32x2 %0,%1,%2;" : "=l"(r) : "l"(a), "l"(b)); return r;
}
__device__ __forceinline__ u64 f2fma(u64 a, u64 b, u64 c) {
    u64 r; asm("fma.rn.f32x2 %0,%1,%2,%3;" : "=l"(r) : "l"(a), "l"(b), "l"(c)); return r;
}
__device__ __forceinline__ u64 f2add(u64 a, u64 b) {
    u64 r; asm("add.rn.f32x2 %0,%1,%2;" : "=l"(r) : "l"(a), "l"(b)); return r;
}

__device__ __forceinline__ float2 cmulf(float2 a, float2 b) {
    return make_float2(fmaf(a.x, b.x, -a.y * b.y), fmaf(a.x, b.y, a.y * b.x));
}

// reduction tree over 16 packed pairs -> scalar (lo+hi)
__device__ __forceinline__ float sumtree16(const u64* R) {
    u64 s0 = f2add(R[0], R[8]);
    u64 s1 = f2add(R[1], R[9]);
    u64 s2 = f2add(R[2], R[10]);
    u64 s3 = f2add(R[3], R[11]);
    u64 s4 = f2add(R[4], R[12]);
    u64 s5 = f2add(R[5], R[13]);
    u64 s6 = f2add(R[6], R[14]);
    u64 s7 = f2add(R[7], R[15]);
    s0 = f2add(s0, s4); s1 = f2add(s1, s5);
    s2 = f2add(s2, s6); s3 = f2add(s3, s7);
    s0 = f2add(s0, s2); s1 = f2add(s1, s3);
    s0 = f2add(s0, s1);
    float lo, hi; upk2(s0, lo, hi);
    return lo + hi;
}

#define PI2_HI 6.2831854820251465f
#define PI2_LO (-1.7484561e-7f)
#define INV2PI 0.15915494309189535f

// accurate sin/cos with two-float 2*pi reduction
__device__ __forceinline__ void redsc(float th, float* s, float* c) {
    float kk = rintf(th * INV2PI);
    float r  = fmaf(-kk, PI2_HI, th);
    r        = fmaf(-kk, PI2_LO, r);
    __sincosf(r, s, c);
}

// per-mode start values from the smem param rows at offset l0f
__device__ __forceinline__ void start_mode(const float4* mpn, float l0f,
                                           float& r0, float& rm,
                                           float& p,  float& q) {
    float4 a = mpn[0];   // p, q, wm32r, wm32i
    float4 b = mpn[1];   // c2r, c2i, dre, dim
    p = a.x; q = a.y;
    float sn, cs;
    redsc(b.w * l0f, &sn, &cs);          // theta = dim*l0 (same rounding as ref)
    float mg  = __expf(b.z * l0f);       // dre*l0 <= 0 -> mg <= 1
    float zr  = mg * cs, zi = mg * sn;
    float z0r = fmaf(b.x, zr, -b.y * zi);
    float z0i = fmaf(b.x, zi,  b.y * zr);
    r0 = z0r;
    rm = fmaf(z0r, a.z, -z0i * a.w);     // Re(z0 * w^-32)
}

__global__ void __launch_bounds__(128, 1)
s4_vandermonde_kernel(const float* __restrict__ log_dt,
                      const float* __restrict__ log_A_real,
                      const float* __restrict__ A_imag,
                      const float* __restrict__ Bmat,
                      const float* __restrict__ Cmat,
                      float* __restrict__ out)
{
    // per warp, per mode: row0 = {p, q, wm32r, wm32i}, row1 = {c2r, c2i, dre, dim}
    __shared__ float4 mp[WPB][NHALF][2];

    const int w = threadIdx.x >> 5;
    const int j = threadIdx.x & 31;
    const int k = blockIdx.x * WPB + w;

    int sg  = (int)(((long long)k       * SEGS_TOT) / NWARPS);
    int sg1 = (int)(((long long)(k + 1) * SEGS_TOT) / NWARPS);

    while (sg < sg1) {
        const int h    = sg >> 3;                 // 8 segments per h
        const int segh = sg & 7;
        const int nseg = min(sg1 - sg, 8 - segh); // segments in this h-span
        const int i0   = segh * SEG_STEPS;        // starting step index

        // ---------- phase A: lane j computes mode j params ----------
        __syncwarp();
        {
            const int n = j;
            const float dt  = __expf(log_dt[h]);
            const float ar  = -__expf(log_A_real[h * NHALF + n]);
            const float aiv = -A_imag[h * NHALF + n];
            const float dre = dt * ar;
            const float dim = dt * aiv;

            float s1v, c1v; redsc(dim, &s1v, &c1v);          // w^1
            float mg1 = __expf(dre);
            float s32, c32; redsc(32.f * dim, &s32, &c32);   // w^32 phase
            float mg32 = __expf(32.f * dre);
            float w32r = mg32 * c32, w32i = mg32 * s32;
            float p = w32r + w32r;
            float q = -fmaf(w32r, w32r, w32i * w32i);
            // w^-32, magnitude clamped (when clamped, q underflowed to 0)
            float mgm = __expf(fminf(-32.f * dre, 60.f));
            float wmr = mgm * c32, wmi = -mgm * s32;
            // 2*Ceff = 2*Bc*Cc*(w-1)/A
            float2 w1  = make_float2(mg1 * c1v, mg1 * s1v);
            float2 num = make_float2(w1.x - 1.0f, w1.y);
            float  inv = 2.0f / fmaf(ar, ar, aiv * aiv);
            float2 ia  = make_float2(ar * inv, -aiv * inv);
            const float2* Bv = (const float2*)Bmat;
            const float2* Cv = (const float2*)Cmat;
            float2 bc  = cmulf(Bv[h * NHALF + n], Cv[h * NHALF + n]);
            float2 c2  = cmulf(cmulf(bc, num), ia);

            mp[w][n][0] = make_float4(p, q, wmr, wmi);
            mp[w][n][1] = make_float4(c2.x, c2.y, dre, dim);
        }
        __syncwarp();

        // ---------- phase B: start state at l0 = 32*i0 + j ----------
        const float l0f = (float)(i0 * 32 + j);
        u64 RB[NHALF / 2], RA[NHALF / 2], P[NHALF / 2], Q[NHALF / 2];
        #pragma unroll
        for (int m = 0; m < NHALF / 2; m++) {
            float r0a, rma, pa, qa, r0b, rmb, pb, qb;
            start_mode(&mp[w][2 * m][0],     l0f, r0a, rma, pa, qa);
            start_mode(&mp[w][2 * m + 1][0], l0f, r0b, rmb, pb, qb);
            RB[m] = pk2(r0a, r0b);
            RA[m] = pk2(rma, rmb);
            P[m]  = pk2(pa, pb);
            Q[m]  = pk2(qa, qb);
        }

        // ---------- segments: STATIC 32-step inner loop, recurrence flows on ----------
        float* opp = out + h * LL + i0 * 32 + j;
        for (int g = 0; g < nseg; g++) {
            #pragma unroll 4
            for (int t = 0; t < SEG_STEPS; t += 2) {
                opp[t * 32] = sumtree16(RB);              // r_t
                #pragma unroll
                for (int m = 0; m < NHALF / 2; m++)       // RA <- r_{t+1}
                    RA[m] = f2fma(P[m], RB[m], f2mul(Q[m], RA[m]));
                opp[(t + 1) * 32] = sumtree16(RA);        // r_{t+1}
                #pragma unroll
                for (int m = 0; m < NHALF / 2; m++)       // RB <- r_{t+2}
                    RB[m] = f2fma(P[m], RA[m], f2mul(Q[m], RB[m]));
            }
            opp += SEG_STEPS * 32;
        }

        sg += nseg;
    }
}

extern "C" void kernel_launch(void* const* d_in, const int* in_sizes, int n_in,
                              void* d_out, int out_size)
{
    const float* log_dt     = (const float*)d_in[0];
    const float* log_A_real = (const float*)d_in[1];
    const float* A_imag     = (const float*)d_in[2];
    const float* Bmat       = (const float*)d_in[3];
    const float* Cmat       = (const float*)d_in[4];
    float* out = (float*)d_out;

    dim3 grid(NBLK);          // 148 blocks -> one per SM
    dim3 block(32 * WPB);     // 128 threads -> one warp per SMSP
    s4_vandermonde_kernel<<<grid, block>>>(log_dt, log_A_real, A_imag,
                                           Bmat, Cmat, out);
}